// round 1
// baseline (speedup 1.0000x reference)
#include <cuda_runtime.h>
#include <math.h>

#define Bv   32
#define Wt   256
#define INF_ 4096
#define Hd   1024
#define Zd   100
#define Dd   100
#define G3   3072      // 3*Hd
#define NS   16        // split-K slices for GRU gemm
#define KSL  64        // K per slice (1024/16)

// ------------------------- scratch (static device memory) -------------------
__device__ float g_xW[(size_t)Wt * Bv * G3];          // [t][b][g]  ~100.7 MB
__device__ float g_h[(size_t)(Wt + 1) * Bv * Hd];     // h_0..h_256 ~33.7 MB
__device__ float g_ghp[(size_t)NS * Bv * G3];         // split-K partials ~6.3 MB
__device__ float g_dh[(size_t)Wt * Bv * Dd];          // denseH ~3.3 MB

// ------------------------- helpers ------------------------------------------
__device__ __forceinline__ void ffma2(unsigned long long &acc,
                                      unsigned long long a,
                                      unsigned long long b) {
    asm("fma.rn.f32x2 %0, %1, %2, %3;" : "=l"(acc) : "l"(a), "l"(b), "l"(acc));
}
__device__ __forceinline__ unsigned long long dup2(float a) {
    unsigned long long r;
    unsigned int ai = __float_as_uint(a);
    asm("mov.b64 %0, {%1, %1};" : "=l"(r) : "r"(ai));
    return r;
}
__device__ __forceinline__ float lo32(unsigned long long v) {
    return __uint_as_float((unsigned int)(v & 0xffffffffULL));
}
__device__ __forceinline__ float hi32(unsigned long long v) {
    return __uint_as_float((unsigned int)(v >> 32));
}

// ------------------------- init: h0 = 0 --------------------------------------
__global__ void k_init() {
    int i = blockIdx.x * blockDim.x + threadIdx.x;
    if (i < Bv * Hd) g_h[i] = 0.f;
}

// ------------------------- K1: xW = x @ W_ih^T + b_ih ------------------------
// C[m][n], m = t*32 + b (M=8192), n = gate row (N=3072), K = 4096.
// BM=128, BN=128, BK=8, 256 threads, 8x8 microtile, f32x2 accumulation.
__global__ __launch_bounds__(256) void k_xw(const float* __restrict__ x,
                                            const float* __restrict__ Wih,
                                            const float* __restrict__ bih) {
    __shared__ float As[8][128];
    __shared__ float Bs[8][128];
    int tid = threadIdx.x;
    int n0 = blockIdx.x * 128;
    int m0 = blockIdx.y * 128;

    // global load indexing
    int aRow = tid >> 1;
    int aK = (tid & 1) * 4;
    int m = m0 + aRow;
    int tt = m >> 5;
    int bb = m & 31;
    const float* aptr = x + ((size_t)bb * Wt + tt) * INF_ + aK;

    int bRow = tid >> 1;
    int bK = (tid & 1) * 4;
    const float* bptr = Wih + (size_t)(n0 + bRow) * INF_ + bK;

    int tr = tid >> 4;   // 0..15 -> rows tr*8..tr*8+7
    int tc = tid & 15;   // 0..15 -> cols tc*8..tc*8+7

    unsigned long long acc[8][4];
#pragma unroll
    for (int i = 0; i < 8; i++)
#pragma unroll
        for (int j = 0; j < 4; j++) acc[i][j] = 0ULL;

    float4 ar = *(const float4*)aptr;
    float4 br = *(const float4*)bptr;

    for (int k0 = 0; k0 < INF_; k0 += 8) {
        As[aK + 0][aRow] = ar.x; As[aK + 1][aRow] = ar.y;
        As[aK + 2][aRow] = ar.z; As[aK + 3][aRow] = ar.w;
        Bs[bK + 0][bRow] = br.x; Bs[bK + 1][bRow] = br.y;
        Bs[bK + 2][bRow] = br.z; Bs[bK + 3][bRow] = br.w;
        __syncthreads();
        if (k0 + 8 < INF_) {
            ar = *(const float4*)(aptr + k0 + 8);
            br = *(const float4*)(bptr + k0 + 8);
        }
#pragma unroll
        for (int k = 0; k < 8; k++) {
            unsigned long long bp[4];
#pragma unroll
            for (int j = 0; j < 4; j++)
                bp[j] = *(const unsigned long long*)&Bs[k][tc * 8 + 2 * j];
#pragma unroll
            for (int i = 0; i < 8; i++) {
                unsigned long long ad = dup2(As[k][tr * 8 + i]);
#pragma unroll
                for (int j = 0; j < 4; j++) ffma2(acc[i][j], ad, bp[j]);
            }
        }
        __syncthreads();
    }

#pragma unroll
    for (int i = 0; i < 8; i++) {
        size_t row = (size_t)(m0 + tr * 8 + i);
#pragma unroll
        for (int j = 0; j < 4; j++) {
            int col = n0 + tc * 8 + 2 * j;
            float2 v;
            v.x = lo32(acc[i][j]) + bih[col];
            v.y = hi32(acc[i][j]) + bih[col + 1];
            *(float2*)&g_xW[row * G3 + col] = v;
        }
    }
}

// ------------------------- K2a: gh partial = h_t @ W_hh^T (split-K) ----------
// grid (24 n-blocks, 16 k-slices). BM=32 (batch), BN=128, K-slice 64.
__global__ __launch_bounds__(256) void k_gh(const float* __restrict__ Whh, int t) {
    __shared__ float Hs[KSL][32];
    __shared__ float Ws[KSL][128];
    int tid = threadIdx.x;
    int n0 = blockIdx.x * 128;
    int ks = blockIdx.y;
    int k0 = ks * KSL;
    const float* h = g_h + (size_t)t * Bv * Hd;

    // load H tile [64 k x 32 b], transposed
    {
        int b = tid >> 3;
        int kk = (tid & 7) * 8;
        float4 v1 = *(const float4*)(h + b * Hd + k0 + kk);
        float4 v2 = *(const float4*)(h + b * Hd + k0 + kk + 4);
        Hs[kk + 0][b] = v1.x; Hs[kk + 1][b] = v1.y;
        Hs[kk + 2][b] = v1.z; Hs[kk + 3][b] = v1.w;
        Hs[kk + 4][b] = v2.x; Hs[kk + 5][b] = v2.y;
        Hs[kk + 6][b] = v2.z; Hs[kk + 7][b] = v2.w;
    }
    // load W tile [128 n x 64 k], transposed
    {
        int n = tid >> 1;
        int kw = (tid & 1) * 4;
        const float* wp = Whh + (size_t)(n0 + n) * Hd + k0;
#pragma unroll
        for (int it = 0; it < 8; it++) {
            float4 v = *(const float4*)(wp + kw + it * 8);
            int kk = kw + it * 8;
            Ws[kk + 0][n] = v.x; Ws[kk + 1][n] = v.y;
            Ws[kk + 2][n] = v.z; Ws[kk + 3][n] = v.w;
        }
    }
    __syncthreads();

    int tr = tid >> 4;  // 0..15 -> batch rows tr*2, tr*2+1
    int tc = tid & 15;  // cols tc*8..+7
    unsigned long long acc[2][4];
#pragma unroll
    for (int i = 0; i < 2; i++)
#pragma unroll
        for (int j = 0; j < 4; j++) acc[i][j] = 0ULL;

#pragma unroll 8
    for (int k = 0; k < KSL; k++) {
        float2 a = *(const float2*)&Hs[k][tr * 2];
        unsigned long long ad0 = dup2(a.x);
        unsigned long long ad1 = dup2(a.y);
        unsigned long long bp[4];
#pragma unroll
        for (int j = 0; j < 4; j++)
            bp[j] = *(const unsigned long long*)&Ws[k][tc * 8 + 2 * j];
#pragma unroll
        for (int j = 0; j < 4; j++) {
            ffma2(acc[0][j], ad0, bp[j]);
            ffma2(acc[1][j], ad1, bp[j]);
        }
    }

#pragma unroll
    for (int i = 0; i < 2; i++) {
        size_t base = ((size_t)ks * Bv + (tr * 2 + i)) * G3;
#pragma unroll
        for (int j = 0; j < 4; j++) {
            int col = n0 + tc * 8 + 2 * j;
            float2 v;
            v.x = lo32(acc[i][j]);
            v.y = hi32(acc[i][j]);
            *(float2*)&g_ghp[base + col] = v;
        }
    }
}

// ------------------------- K2b: gate fusion -> h_{t+1} -----------------------
__global__ void k_gate(const float* __restrict__ bhh, int t) {
    int idx = blockIdx.x * blockDim.x + threadIdx.x;  // 0..32767
    int b = idx >> 10;
    int ii = idx & 1023;
    float sr = 0.f, sz = 0.f, sn = 0.f;
#pragma unroll
    for (int ks = 0; ks < NS; ks++) {
        const float* p = g_ghp + ((size_t)ks * Bv + b) * G3;
        sr += p[ii];
        sz += p[Hd + ii];
        sn += p[2 * Hd + ii];
    }
    const float* gi = g_xW + ((size_t)t * Bv + b) * G3;
    float gr = gi[ii] + sr + bhh[ii];
    float gz = gi[Hd + ii] + sz + bhh[Hd + ii];
    float gnh = sn + bhh[2 * Hd + ii];
    float r = 1.f / (1.f + __expf(-gr));
    float z = 1.f / (1.f + __expf(-gz));
    float n = tanhf(gi[2 * Hd + ii] + r * gnh);
    float hp = g_h[(size_t)t * Bv * Hd + b * Hd + ii];
    g_h[(size_t)(t + 1) * Bv * Hd + b * Hd + ii] = (1.f - z) * n + z * hp;
}

// ------------------------- K3: denseH = h_all @ Wd[:,100:]^T + bd ------------
// M=8192 (t,b), N=100 (padded 128), K=1024. BM=64, BN=128, BK=8.
__global__ __launch_bounds__(256) void k_dh(const float* __restrict__ Wd,
                                            const float* __restrict__ bd) {
    __shared__ float As[8][64];
    __shared__ float Bs[8][128];
    int tid = threadIdx.x;
    int m0 = blockIdx.x * 64;
    const float* hall = g_h + (size_t)Bv * Hd;  // h_1..h_256

    int aRow = tid >> 2;        // 0..63
    int aK = (tid & 3) * 2;     // 0,2,4,6
    const float* aptr = hall + (size_t)(m0 + aRow) * Hd + aK;

    int bRow = tid >> 1;        // 0..127
    int bK = (tid & 1) * 4;
    const float* bptr = Wd + (size_t)bRow * (Zd + Hd) + Zd + bK;
    bool bValid = (bRow < Dd);

    int tr = tid >> 4;  // 0..15 -> rows tr*4..+3
    int tc = tid & 15;  // cols tc*8..+7

    unsigned long long acc[4][4];
#pragma unroll
    for (int i = 0; i < 4; i++)
#pragma unroll
        for (int j = 0; j < 4; j++) acc[i][j] = 0ULL;

    float2 ar = *(const float2*)aptr;
    float4 br = bValid ? *(const float4*)bptr : make_float4(0.f, 0.f, 0.f, 0.f);

    for (int k0 = 0; k0 < Hd; k0 += 8) {
        As[aK + 0][aRow] = ar.x; As[aK + 1][aRow] = ar.y;
        Bs[bK + 0][bRow] = br.x; Bs[bK + 1][bRow] = br.y;
        Bs[bK + 2][bRow] = br.z; Bs[bK + 3][bRow] = br.w;
        __syncthreads();
        if (k0 + 8 < Hd) {
            ar = *(const float2*)(aptr + k0 + 8);
            br = bValid ? *(const float4*)(bptr + k0 + 8)
                        : make_float4(0.f, 0.f, 0.f, 0.f);
        }
#pragma unroll
        for (int k = 0; k < 8; k++) {
            unsigned long long bp[4];
#pragma unroll
            for (int j = 0; j < 4; j++)
                bp[j] = *(const unsigned long long*)&Bs[k][tc * 8 + 2 * j];
#pragma unroll
            for (int i = 0; i < 4; i++) {
                unsigned long long ad = dup2(As[k][tr * 4 + i]);
#pragma unroll
                for (int j = 0; j < 4; j++) ffma2(acc[i][j], ad, bp[j]);
            }
        }
        __syncthreads();
    }

#pragma unroll
    for (int i = 0; i < 4; i++) {
        size_t row = (size_t)(m0 + tr * 4 + i);
#pragma unroll
        for (int j = 0; j < 4; j++) {
            int col = tc * 8 + 2 * j;
            if (col < Dd) {
                g_dh[row * Dd + col] = lo32(acc[i][j]) + bd[col];
                g_dh[row * Dd + col + 1] = hi32(acc[i][j]) + bd[col + 1];
            }
        }
    }
}

// ------------------------- K4: batch-parallel z-chain ------------------------
// 32 CTAs (one per batch row), 128 threads, 256 sequential steps.
__global__ void k_head(const float* __restrict__ Wd,
                       const float* __restrict__ Wmu, const float* __restrict__ bmu,
                       const float* __restrict__ Wsig, const float* __restrict__ bsig,
                       const float* __restrict__ u,
                       const float* __restrict__ Wpnf, const float* __restrict__ bpnf,
                       const float* __restrict__ noise,
                       float* __restrict__ out) {
    extern __shared__ float sm[];
    float* Wdz = sm;                  // [k][j] 100x100
    float* Wmu_t = Wdz + 10000;
    float* Wsg_t = Wmu_t + 10000;
    float* Wpf_t = Wsg_t + 10000;
    float* zb = Wpf_t + 10000;        // 104
    float* dn = zb + 104;             // 104
    float* zm = dn + 104;             // 104

    int b = blockIdx.x;
    int tid = threadIdx.x;

    for (int i = tid; i < 10000; i += 128) {
        int j = i / 100, k = i - j * 100;
        Wdz[k * 100 + j] = Wd[(size_t)j * (Zd + Hd) + k];
        Wmu_t[k * 100 + j] = Wmu[(size_t)j * 100 + k];
        Wsg_t[k * 100 + j] = Wsig[(size_t)j * 100 + k];
        Wpf_t[k * 100 + j] = Wpnf[(size_t)j * 100 + k];
    }
    if (tid < 100) zb[tid] = 0.f;
    __syncthreads();

    float u0 = u[0];
    const size_t BWZ = (size_t)Bv * Wt * Zd;

    for (int t = 0; t < Wt; t++) {
        if (tid < 100) {
            float s = g_dh[((size_t)t * Bv + b) * Dd + tid];
#pragma unroll 4
            for (int k = 0; k < 100; k++) s += zb[k] * Wdz[k * 100 + tid];
            dn[tid] = s;
        }
        __syncthreads();
        if (tid < 100) {
            float smu = bmu[tid], ssg = bsig[tid];
#pragma unroll 4
            for (int k = 0; k < 100; k++) {
                float d = dn[k];
                smu += d * Wmu_t[k * 100 + tid];
                ssg += d * Wsg_t[k * 100 + tid];
            }
            // softplus (numerically stable)
            float lv = fmaxf(ssg, 0.f) + log1pf(expf(-fabsf(ssg)));
            float eps = noise[((size_t)t * Bv + b) * Zd + tid];
            float zmid = smu + expf(0.5f * lv) * eps;
            zm[tid] = zmid;
            size_t o = ((size_t)b * Wt + t) * Zd + tid;
            out[BWZ + o] = smu;
            out[2 * BWZ + o] = lv;
        }
        __syncthreads();
        if (tid < 100) {
            float s = bpnf[tid];
#pragma unroll 4
            for (int k = 0; k < 100; k++) s += zm[k] * Wpf_t[k * 100 + tid];
            float zn = zm[tid] + u0 * tanhf(s);
            zb[tid] = zn;
            out[((size_t)b * Wt + t) * Zd + tid] = zn;
        }
        __syncthreads();
    }
}

// ------------------------- launch -------------------------------------------
extern "C" void kernel_launch(void* const* d_in, const int* in_sizes, int n_in,
                              void* d_out, int out_size) {
    const float* x = (const float*)d_in[0];
    const float* Wih = (const float*)d_in[1];
    const float* Whh = (const float*)d_in[2];
    const float* bih = (const float*)d_in[3];
    const float* bhh = (const float*)d_in[4];
    const float* Wd = (const float*)d_in[5];
    const float* bd = (const float*)d_in[6];
    const float* Wmu = (const float*)d_in[7];
    const float* bmu = (const float*)d_in[8];
    const float* Wsig = (const float*)d_in[9];
    const float* bsig = (const float*)d_in[10];
    const float* u = (const float*)d_in[11];
    const float* Wpnf = (const float*)d_in[12];
    const float* bpnf = (const float*)d_in[13];
    const float* noise = (const float*)d_in[14];
    float* out = (float*)d_out;

    k_init<<<(Bv * Hd + 255) / 256, 256>>>();
    k_xw<<<dim3(G3 / 128, (Wt * Bv) / 128), 256>>>(x, Wih, bih);
    for (int t = 0; t < Wt; t++) {
        k_gh<<<dim3(G3 / 128, NS), 256>>>(Whh, t);
        k_gate<<<(Bv * Hd) / 256, 256>>>(bhh, t);
    }
    k_dh<<<(Wt * Bv) / 64, 256>>>(Wd, bd);

    int smem_head = (4 * 10000 + 3 * 104) * (int)sizeof(float);
    cudaFuncSetAttribute(k_head, cudaFuncAttributeMaxDynamicSharedMemorySize,
                         smem_head);
    k_head<<<Bv, 128, smem_head>>>(Wd, Wmu, bmu, Wsig, bsig, u, Wpnf, bpnf,
                                   noise, out);
}

// round 5
// speedup vs baseline: 1.2727x; 1.2727x over previous
#include <cuda_runtime.h>
#include <math.h>

#define Bv   32
#define Wt   256
#define INF_ 4096
#define Hd   1024
#define Zd   100
#define Dd   100
#define G3   3072
#define NCTA 128
#define TPB  256

typedef unsigned long long u64;

// ------------------------- scratch (static device memory) -------------------
__device__ float g_xW[(size_t)Wt * Bv * G3];          // [t][b][g]
__device__ float g_h[(size_t)(Wt + 1) * Bv * Hd];     // h_0..h_256
__device__ float g_dh[(size_t)Wt * Bv * Dd];          // denseH
__device__ unsigned g_barCount;
__device__ volatile unsigned g_barGen;

// ------------------------- helpers ------------------------------------------
__device__ __forceinline__ void ffma2(u64 &acc, u64 a, u64 b) {
    asm("fma.rn.f32x2 %0, %1, %2, %3;" : "=l"(acc) : "l"(a), "l"(b), "l"(acc));
}
__device__ __forceinline__ u64 dup2(float a) {
    u64 r;
    unsigned int ai = __float_as_uint(a);
    asm("mov.b64 %0, {%1, %1};" : "=l"(r) : "r"(ai));
    return r;
}
__device__ __forceinline__ float lo32(u64 v) {
    return __uint_as_float((unsigned int)(v & 0xffffffffULL));
}
__device__ __forceinline__ float hi32(u64 v) {
    return __uint_as_float((unsigned int)(v >> 32));
}

// ------------------------- init ----------------------------------------------
__global__ void k_init() {
    int i = blockIdx.x * blockDim.x + threadIdx.x;
    if (i < Bv * Hd) g_h[i] = 0.f;
    if (i == 0) { g_barCount = 0; g_barGen = 0; }
}

// ------------------------- K1: xW = x @ W_ih^T + b_ih ------------------------
__global__ __launch_bounds__(256) void k_xw(const float* __restrict__ x,
                                            const float* __restrict__ Wih,
                                            const float* __restrict__ bih) {
    __shared__ float As[8][128];
    __shared__ float Bs[8][128];
    int tid = threadIdx.x;
    int n0 = blockIdx.x * 128;
    int m0 = blockIdx.y * 128;

    int aRow = tid >> 1;
    int aK = (tid & 1) * 4;
    int m = m0 + aRow;
    int tt = m >> 5;
    int bb = m & 31;
    const float* aptr = x + ((size_t)bb * Wt + tt) * INF_ + aK;

    int bRow = tid >> 1;
    int bK = (tid & 1) * 4;
    const float* bptr = Wih + (size_t)(n0 + bRow) * INF_ + bK;

    int tr = tid >> 4;
    int tc = tid & 15;

    u64 acc[8][4];
#pragma unroll
    for (int i = 0; i < 8; i++)
#pragma unroll
        for (int j = 0; j < 4; j++) acc[i][j] = 0ULL;

    float4 ar = *(const float4*)aptr;
    float4 br = *(const float4*)bptr;

    for (int k0 = 0; k0 < INF_; k0 += 8) {
        As[aK + 0][aRow] = ar.x; As[aK + 1][aRow] = ar.y;
        As[aK + 2][aRow] = ar.z; As[aK + 3][aRow] = ar.w;
        Bs[bK + 0][bRow] = br.x; Bs[bK + 1][bRow] = br.y;
        Bs[bK + 2][bRow] = br.z; Bs[bK + 3][bRow] = br.w;
        __syncthreads();
        if (k0 + 8 < INF_) {
            ar = *(const float4*)(aptr + k0 + 8);
            br = *(const float4*)(bptr + k0 + 8);
        }
#pragma unroll
        for (int k = 0; k < 8; k++) {
            u64 bp[4];
#pragma unroll
            for (int j = 0; j < 4; j++)
                bp[j] = *(const u64*)&Bs[k][tc * 8 + 2 * j];
#pragma unroll
            for (int i = 0; i < 8; i++) {
                u64 ad = dup2(As[k][tr * 8 + i]);
#pragma unroll
                for (int j = 0; j < 4; j++) ffma2(acc[i][j], ad, bp[j]);
            }
        }
        __syncthreads();
    }

#pragma unroll
    for (int i = 0; i < 8; i++) {
        size_t row = (size_t)(m0 + tr * 8 + i);
#pragma unroll
        for (int j = 0; j < 4; j++) {
            int col = n0 + tc * 8 + 2 * j;
            float2 v;
            v.x = lo32(acc[i][j]) + bih[col];
            v.y = hi32(acc[i][j]) + bih[col + 1];
            *(float2*)&g_xW[row * G3 + col] = v;
        }
    }
}

// ------------------------- K2: persistent fused GRU recurrence ---------------
// 128 CTAs x 256 threads. CTA bx owns output columns [bx*8, bx*8+8) of each gate.
// W_hh slice resident in SMEM for all 256 steps. One software grid barrier/step.
//
// thread mapping: b = tid&31, ipair = (tid>>5)&3, half = tid>>7
//   -> output cols i0 = bx*8 + ipair*2, i1 = i0+1 ; k range = half of 1024.
//
// smem: Wq  [3 gates][4 ipairs][512 k2][4]  (quad = {Wi0k0,Wi1k0,Wi0k1,Wi1k1})
//       hb  [2 bufs][32 b][260]            (chunked h staging, 256k + pad)
//       red [128][6]                       (half-reduction)
#define HB_STRIDE 260
#define HB_BUF    (32 * HB_STRIDE)
#define WQ_FLOATS (3 * 4 * 512 * 4)
#define RNN_SMEM  ((WQ_FLOATS + 2 * HB_BUF + 128 * 6) * 4)

__device__ __forceinline__ void gridBarrier() {
    __syncthreads();
    if (threadIdx.x == 0) {
        __threadfence();
        unsigned gen = g_barGen;
        if (atomicAdd(&g_barCount, 1u) == NCTA - 1) {
            g_barCount = 0;
            __threadfence();
            g_barGen = gen + 1;
        } else {
            while (g_barGen == gen) { }
        }
    }
    __syncthreads();
}

__global__ __launch_bounds__(TPB, 1) void k_rnn(const float* __restrict__ Whh,
                                                const float* __restrict__ bhh) {
    extern __shared__ float sm[];
    float* Wq = sm;                       // 24576 floats
    float* hb = Wq + WQ_FLOATS;           // 2*8320 floats
    float* red = hb + 2 * HB_BUF;         // 768 floats
    ulonglong2* Wq2 = (ulonglong2*)Wq;

    int tid = threadIdx.x;
    int bx = blockIdx.x;
    int b = tid & 31;
    int ipair = (tid >> 5) & 3;
    int half = tid >> 7;
    int i0 = bx * 8 + ipair * 2;

    // ---- load W_hh slice into smem quads (once) ----
    for (int q = tid; q < 3 * 4 * 512; q += TPB) {
        int g = q >> 11;            // /2048
        int rem = q & 2047;
        int p = rem >> 9;
        int k2 = rem & 511;
        const float* w0 = Whh + (size_t)(g * Hd + bx * 8 + p * 2) * Hd + 2 * k2;
        float2 a = *(const float2*)w0;
        float2 c = *(const float2*)(w0 + Hd);
        float4 vq = make_float4(a.x, c.x, a.y, c.y);
        *(float4*)&Wq[q * 4] = vq;
    }

    // per-thread constant biases (half 0 only uses them)
    float bh_r0 = bhh[i0], bh_r1 = bhh[i0 + 1];
    float bh_z0 = bhh[Hd + i0], bh_z1 = bhh[Hd + i0 + 1];
    float bh_n0 = bhh[2 * Hd + i0], bh_n1 = bhh[2 * Hd + i0 + 1];
    __syncthreads();

    for (int t = 0; t < Wt; t++) {
        const float* hsrc = g_h + (size_t)t * Bv * Hd;

        // prefetch gi + h_prev for the gate stage (consumed after reduction)
        float2 gir, giz, gin, hp2;
        if (half == 0) {
            const float* gi = g_xW + ((size_t)t * Bv + b) * G3 + i0;
            gir = __ldcg((const float2*)gi);
            giz = __ldcg((const float2*)(gi + Hd));
            gin = __ldcg((const float2*)(gi + 2 * Hd));
            hp2 = __ldcg((const float2*)(hsrc + b * Hd + i0));
        }

        u64 acc0 = 0ULL, acc1 = 0ULL, acc2 = 0ULL;

        // ---- stage chunk 0 ----
#pragma unroll
        for (int j = 0; j < 8; j++) {
            int e = (j * TPB + tid) * 4;        // element in chunk (floats)
            int eb = e >> 8;
            int ek = e & 255;
            float4 v = __ldcg((const float4*)(hsrc + eb * Hd + ek));
            *(float4*)&hb[eb * HB_STRIDE + ek] = v;
        }
        __syncthreads();

        for (int c = 0; c < 4; c++) {
            int buf = c & 1;
            // stage next chunk into other buffer (overlaps with compute)
            if (c < 3) {
                int nbuf = buf ^ 1;
                int kofs = (c + 1) * 256;
#pragma unroll
                for (int j = 0; j < 8; j++) {
                    int e = (j * TPB + tid) * 4;
                    int eb = e >> 8;
                    int ek = e & 255;
                    float4 v = __ldcg((const float4*)(hsrc + eb * Hd + kofs + ek));
                    *(float4*)&hb[nbuf * HB_BUF + eb * HB_STRIDE + ek] = v;
                }
            }
            // ---- compute 64 k2 (=128 k) of this chunk ----
            const float* hrow = &hb[buf * HB_BUF + b * HB_STRIDE + half * 128];
            int wbase = c * 128 + half * 64;
#pragma unroll 8
            for (int k2 = 0; k2 < 64; k2++) {
                float2 hv = *(const float2*)&hrow[2 * k2];
                u64 d0 = dup2(hv.x);
                u64 d1 = dup2(hv.y);
                int kk = wbase + k2;
                ulonglong2 qr = Wq2[(0 * 4 + ipair) * 512 + kk];
                ulonglong2 qz = Wq2[(1 * 4 + ipair) * 512 + kk];
                ulonglong2 qn = Wq2[(2 * 4 + ipair) * 512 + kk];
                ffma2(acc0, d0, qr.x); ffma2(acc0, d1, qr.y);
                ffma2(acc1, d0, qz.x); ffma2(acc1, d1, qz.y);
                ffma2(acc2, d0, qn.x); ffma2(acc2, d1, qn.y);
            }
            __syncthreads();
        }

        // ---- reduce halves ----
        if (half == 1) {
            float* r = &red[(tid - 128) * 6];
            r[0] = lo32(acc0); r[1] = hi32(acc0);
            r[2] = lo32(acc1); r[3] = hi32(acc1);
            r[4] = lo32(acc2); r[5] = hi32(acc2);
        }
        __syncthreads();

        if (half == 0) {
            const float* r = &red[tid * 6];
            float sr0 = lo32(acc0) + r[0], sr1 = hi32(acc0) + r[1];
            float sz0 = lo32(acc1) + r[2], sz1 = hi32(acc1) + r[3];
            float sn0 = lo32(acc2) + r[4], sn1 = hi32(acc2) + r[5];

            float gr0 = gir.x + sr0 + bh_r0;
            float gr1 = gir.y + sr1 + bh_r1;
            float gz0 = giz.x + sz0 + bh_z0;
            float gz1 = giz.y + sz1 + bh_z1;
            float rr0 = 1.f / (1.f + __expf(-gr0));
            float rr1 = 1.f / (1.f + __expf(-gr1));
            float zz0 = 1.f / (1.f + __expf(-gz0));
            float zz1 = 1.f / (1.f + __expf(-gz1));
            float nn0 = tanhf(gin.x + rr0 * (sn0 + bh_n0));
            float nn1 = tanhf(gin.y + rr1 * (sn1 + bh_n1));
            float2 hn;
            hn.x = (1.f - zz0) * nn0 + zz0 * hp2.x;
            hn.y = (1.f - zz1) * nn1 + zz1 * hp2.y;
            *(float2*)(g_h + (size_t)(t + 1) * Bv * Hd + b * Hd + i0) = hn;
        }

        gridBarrier();
    }
}

// ------------------------- K3: denseH = h_all @ Wd[:,100:]^T + bd ------------
__global__ __launch_bounds__(256) void k_dh(const float* __restrict__ Wd,
                                            const float* __restrict__ bd) {
    __shared__ float As[8][64];
    __shared__ float Bs[8][128];
    int tid = threadIdx.x;
    int m0 = blockIdx.x * 64;
    const float* hall = g_h + (size_t)Bv * Hd;

    int aRow = tid >> 2;
    int aK = (tid & 3) * 2;
    const float* aptr = hall + (size_t)(m0 + aRow) * Hd + aK;

    int bRow = tid >> 1;
    int bK = (tid & 1) * 4;
    const float* bptr = Wd + (size_t)bRow * (Zd + Hd) + Zd + bK;
    bool bValid = (bRow < Dd);

    int tr = tid >> 4;
    int tc = tid & 15;

    u64 acc[4][4];
#pragma unroll
    for (int i = 0; i < 4; i++)
#pragma unroll
        for (int j = 0; j < 4; j++) acc[i][j] = 0ULL;

    float2 ar = *(const float2*)aptr;
    float4 br = bValid ? *(const float4*)bptr : make_float4(0.f, 0.f, 0.f, 0.f);

    for (int k0 = 0; k0 < Hd; k0 += 8) {
        As[aK + 0][aRow] = ar.x; As[aK + 1][aRow] = ar.y;
        Bs[bK + 0][bRow] = br.x; Bs[bK + 1][bRow] = br.y;
        Bs[bK + 2][bRow] = br.z; Bs[bK + 3][bRow] = br.w;
        __syncthreads();
        if (k0 + 8 < Hd) {
            ar = *(const float2*)(aptr + k0 + 8);
            br = bValid ? *(const float4*)(bptr + k0 + 8)
                        : make_float4(0.f, 0.f, 0.f, 0.f);
        }
#pragma unroll
        for (int k = 0; k < 8; k++) {
            u64 bp[4];
#pragma unroll
            for (int j = 0; j < 4; j++)
                bp[j] = *(const u64*)&Bs[k][tc * 8 + 2 * j];
#pragma unroll
            for (int i = 0; i < 4; i++) {
                u64 ad = dup2(As[k][tr * 4 + i]);
#pragma unroll
                for (int j = 0; j < 4; j++) ffma2(acc[i][j], ad, bp[j]);
            }
        }
        __syncthreads();
    }

#pragma unroll
    for (int i = 0; i < 4; i++) {
        size_t row = (size_t)(m0 + tr * 4 + i);
#pragma unroll
        for (int j = 0; j < 4; j++) {
            int col = tc * 8 + 2 * j;
            if (col < Dd) {
                g_dh[row * Dd + col] = lo32(acc[i][j]) + bd[col];
                g_dh[row * Dd + col + 1] = hi32(acc[i][j]) + bd[col + 1];
            }
        }
    }
}

// ------------------------- K4: batch-parallel z-chain ------------------------
__global__ void k_head(const float* __restrict__ Wd,
                       const float* __restrict__ Wmu, const float* __restrict__ bmu,
                       const float* __restrict__ Wsig, const float* __restrict__ bsig,
                       const float* __restrict__ u,
                       const float* __restrict__ Wpnf, const float* __restrict__ bpnf,
                       const float* __restrict__ noise,
                       float* __restrict__ out) {
    extern __shared__ float sm[];
    float* Wdz = sm;
    float* Wmu_t = Wdz + 10000;
    float* Wsg_t = Wmu_t + 10000;
    float* Wpf_t = Wsg_t + 10000;
    float* zb = Wpf_t + 10000;
    float* dn = zb + 104;
    float* zm = dn + 104;

    int b = blockIdx.x;
    int tid = threadIdx.x;

    for (int i = tid; i < 10000; i += 128) {
        int j = i / 100, k = i - j * 100;
        Wdz[k * 100 + j] = Wd[(size_t)j * (Zd + Hd) + k];
        Wmu_t[k * 100 + j] = Wmu[(size_t)j * 100 + k];
        Wsg_t[k * 100 + j] = Wsig[(size_t)j * 100 + k];
        Wpf_t[k * 100 + j] = Wpnf[(size_t)j * 100 + k];
    }
    if (tid < 100) zb[tid] = 0.f;
    __syncthreads();

    float u0 = u[0];
    const size_t BWZ = (size_t)Bv * Wt * Zd;

    for (int t = 0; t < Wt; t++) {
        if (tid < 100) {
            float s = g_dh[((size_t)t * Bv + b) * Dd + tid];
#pragma unroll 4
            for (int k = 0; k < 100; k++) s += zb[k] * Wdz[k * 100 + tid];
            dn[tid] = s;
        }
        __syncthreads();
        if (tid < 100) {
            float smu = bmu[tid], ssg = bsig[tid];
#pragma unroll 4
            for (int k = 0; k < 100; k++) {
                float d = dn[k];
                smu += d * Wmu_t[k * 100 + tid];
                ssg += d * Wsg_t[k * 100 + tid];
            }
            float lv = fmaxf(ssg, 0.f) + log1pf(expf(-fabsf(ssg)));
            float eps = noise[((size_t)t * Bv + b) * Zd + tid];
            float zmid = smu + expf(0.5f * lv) * eps;
            zm[tid] = zmid;
            size_t o = ((size_t)b * Wt + t) * Zd + tid;
            out[BWZ + o] = smu;
            out[2 * BWZ + o] = lv;
        }
        __syncthreads();
        if (tid < 100) {
            float s = bpnf[tid];
#pragma unroll 4
            for (int k = 0; k < 100; k++) s += zm[k] * Wpf_t[k * 100 + tid];
            float zn = zm[tid] + u0 * tanhf(s);
            zb[tid] = zn;
            out[((size_t)b * Wt + t) * Zd + tid] = zn;
        }
        __syncthreads();
    }
}

// ------------------------- launch -------------------------------------------
extern "C" void kernel_launch(void* const* d_in, const int* in_sizes, int n_in,
                              void* d_out, int out_size) {
    const float* x = (const float*)d_in[0];
    const float* Wih = (const float*)d_in[1];
    const float* Whh = (const float*)d_in[2];
    const float* bih = (const float*)d_in[3];
    const float* bhh = (const float*)d_in[4];
    const float* Wd = (const float*)d_in[5];
    const float* bd = (const float*)d_in[6];
    const float* Wmu = (const float*)d_in[7];
    const float* bmu = (const float*)d_in[8];
    const float* Wsig = (const float*)d_in[9];
    const float* bsig = (const float*)d_in[10];
    const float* u = (const float*)d_in[11];
    const float* Wpnf = (const float*)d_in[12];
    const float* bpnf = (const float*)d_in[13];
    const float* noise = (const float*)d_in[14];
    float* out = (float*)d_out;

    k_init<<<(Bv * Hd + 255) / 256, 256>>>();
    k_xw<<<dim3(G3 / 128, (Wt * Bv) / 128), 256>>>(x, Wih, bih);

    cudaFuncSetAttribute(k_rnn, cudaFuncAttributeMaxDynamicSharedMemorySize,
                         RNN_SMEM);
    k_rnn<<<NCTA, TPB, RNN_SMEM>>>(Whh, bhh);

    k_dh<<<(Wt * Bv) / 64, 256>>>(Wd, bd);

    int smem_head = (4 * 10000 + 3 * 104) * (int)sizeof(float);
    cudaFuncSetAttribute(k_head, cudaFuncAttributeMaxDynamicSharedMemorySize,
                         smem_head);
    k_head<<<Bv, 128, smem_head>>>(Wd, Wmu, bmu, Wsig, bsig, u, Wpnf, bpnf,
                                   noise, out);
}

// round 6
// speedup vs baseline: 1.3996x; 1.0997x over previous
#include <cuda_runtime.h>
#include <math.h>

#define Bv   32
#define Wt   256
#define INF_ 4096
#define Hd   1024
#define Zd   100
#define Dd   100
#define G3   3072
#define NCTA 128
#define TPB  256

typedef unsigned long long u64;

// ------------------------- scratch (static device memory) -------------------
// h stored TRANSPOSED: hT[t][k][b]  (k = 0..1023, b = 0..31)
__device__ float g_xW[(size_t)Wt * Bv * G3];          // [t*32+b][g]
__device__ float g_h[(size_t)(Wt + 1) * Hd * Bv];     // hT
__device__ float g_dh[(size_t)Wt * Bv * Dd];          // denseH
__device__ unsigned g_barCount;
__device__ volatile unsigned g_barGen;

// ------------------------- helpers ------------------------------------------
__device__ __forceinline__ void ffma2(u64 &acc, u64 a, u64 b) {
    asm("fma.rn.f32x2 %0, %1, %2, %3;" : "=l"(acc) : "l"(a), "l"(b), "l"(acc));
}
__device__ __forceinline__ u64 fadd2(u64 a, u64 b) {
    u64 r;
    asm("add.rn.f32x2 %0, %1, %2;" : "=l"(r) : "l"(a), "l"(b));
    return r;
}
__device__ __forceinline__ u64 dup2(float a) {
    u64 r;
    unsigned int ai = __float_as_uint(a);
    asm("mov.b64 %0, {%1, %1};" : "=l"(r) : "r"(ai));
    return r;
}
__device__ __forceinline__ float lo32(u64 v) {
    return __uint_as_float((unsigned int)(v & 0xffffffffULL));
}
__device__ __forceinline__ float hi32(u64 v) {
    return __uint_as_float((unsigned int)(v >> 32));
}

// ------------------------- init: hT[0] = 0 -----------------------------------
__global__ void k_init() {
    int i = blockIdx.x * blockDim.x + threadIdx.x;
    if (i < Bv * Hd) g_h[i] = 0.f;
    if (i == 0) { g_barCount = 0; g_barGen = 0; }
}

// ------------------------- K1: xW = x @ W_ih^T + b_ih ------------------------
__global__ __launch_bounds__(256) void k_xw(const float* __restrict__ x,
                                            const float* __restrict__ Wih,
                                            const float* __restrict__ bih) {
    __shared__ float As[8][128];
    __shared__ float Bs[8][128];
    int tid = threadIdx.x;
    int n0 = blockIdx.x * 128;
    int m0 = blockIdx.y * 128;

    int aRow = tid >> 1;
    int aK = (tid & 1) * 4;
    int m = m0 + aRow;
    int tt = m >> 5;
    int bb = m & 31;
    const float* aptr = x + ((size_t)bb * Wt + tt) * INF_ + aK;

    int bRow = tid >> 1;
    int bK = (tid & 1) * 4;
    const float* bptr = Wih + (size_t)(n0 + bRow) * INF_ + bK;

    int tr = tid >> 4;
    int tc = tid & 15;

    u64 acc[8][4];
#pragma unroll
    for (int i = 0; i < 8; i++)
#pragma unroll
        for (int j = 0; j < 4; j++) acc[i][j] = 0ULL;

    float4 ar = *(const float4*)aptr;
    float4 br = *(const float4*)bptr;

    for (int k0 = 0; k0 < INF_; k0 += 8) {
        As[aK + 0][aRow] = ar.x; As[aK + 1][aRow] = ar.y;
        As[aK + 2][aRow] = ar.z; As[aK + 3][aRow] = ar.w;
        Bs[bK + 0][bRow] = br.x; Bs[bK + 1][bRow] = br.y;
        Bs[bK + 2][bRow] = br.z; Bs[bK + 3][bRow] = br.w;
        __syncthreads();
        if (k0 + 8 < INF_) {
            ar = *(const float4*)(aptr + k0 + 8);
            br = *(const float4*)(bptr + k0 + 8);
        }
#pragma unroll
        for (int k = 0; k < 8; k++) {
            u64 bp[4];
#pragma unroll
            for (int j = 0; j < 4; j++)
                bp[j] = *(const u64*)&Bs[k][tc * 8 + 2 * j];
#pragma unroll
            for (int i = 0; i < 8; i++) {
                u64 ad = dup2(As[k][tr * 8 + i]);
#pragma unroll
                for (int j = 0; j < 4; j++) ffma2(acc[i][j], ad, bp[j]);
            }
        }
        __syncthreads();
    }

#pragma unroll
    for (int i = 0; i < 8; i++) {
        size_t row = (size_t)(m0 + tr * 8 + i);
#pragma unroll
        for (int j = 0; j < 4; j++) {
            int col = n0 + tc * 8 + 2 * j;
            float2 v;
            v.x = lo32(acc[i][j]) + bih[col];
            v.y = hi32(acc[i][j]) + bih[col + 1];
            *(float2*)&g_xW[row * G3 + col] = v;
        }
    }
}

// ------------------------- K2: persistent fused GRU recurrence ---------------
// 128 CTAs. CTA bx owns cols [bx*8, bx*8+8) of each gate.
// Thread: slice = tid>>4 (K-split 16), l = tid&15 -> bg = l&3 (8 batches),
//         cg = l>>2 (col pair).  Accs: 3 gates x 8 batches f32x2.
// W packed in smem as u64 col-pairs: Wp[(g*4+cg)*1026 + k]   (96KB+pad)
// h staged per 256-k chunk into smem rows of 36 floats (hT layout copy).
#define WPS      1026
#define WP_U64   (12 * WPS)
#define HBROW    36
#define HBN      (256 * HBROW)
#define RNN_SMEM (WP_U64 * 8 + 2 * HBN * 4)

__device__ __forceinline__ void gridBarrier() {
    __syncthreads();
    if (threadIdx.x == 0) {
        __threadfence();
        unsigned gen = g_barGen;
        if (atomicAdd(&g_barCount, 1u) == NCTA - 1) {
            g_barCount = 0;
            __threadfence();
            g_barGen = gen + 1;
        } else {
            while (g_barGen == gen) { }
        }
    }
    __syncthreads();
}

__global__ __launch_bounds__(TPB, 1) void k_rnn(const float* __restrict__ Whh,
                                                const float* __restrict__ bhh) {
    extern __shared__ float sm[];
    u64* Wp = (u64*)sm;
    float* hb = sm + WP_U64 * 2;          // (u64 -> 2 floats)
    u64* red = (u64*)hb;                  // overlays hb buf0 after compute

    int tid = threadIdx.x;
    int bx = blockIdx.x;
    int l = tid & 15;
    int bg = l & 3;
    int cg = l >> 2;
    int sbase = (tid >> 4) * 16;          // slice * 16 (k-offset in chunk)

    // ---- pack W_hh col-pairs into smem (once) ----
    for (int q = tid; q < 12 * Hd; q += TPB) {
        int row = q >> 10;                // g*4+cgq
        int k = q & 1023;
        int g = row >> 2;
        int c = bx * 8 + (row & 3) * 2;
        float lo = Whh[((size_t)g * Hd + c) * Hd + k];
        float hi = Whh[((size_t)g * Hd + c + 1) * Hd + k];
        u64 v;
        asm("mov.b64 %0, {%1, %2};" : "=l"(v)
            : "r"(__float_as_uint(lo)), "r"(__float_as_uint(hi)));
        Wp[row * WPS + k] = v;
    }

    // ---- final-stage thread identity + constants ----
    int fcg = tid >> 5;                   // 0..3 (valid for tid<128)
    int fb = tid & 31;
    int fi0 = bx * 8 + fcg * 2;
    int flsel = fcg * 4 + (fb >> 3);
    int fbi = fb & 7;
    float bhr0 = 0, bhr1 = 0, bhz0 = 0, bhz1 = 0, bhn0 = 0, bhn1 = 0;
    if (tid < 128) {
        bhr0 = bhh[fi0];          bhr1 = bhh[fi0 + 1];
        bhz0 = bhh[Hd + fi0];     bhz1 = bhh[Hd + fi0 + 1];
        bhn0 = bhh[2 * Hd + fi0]; bhn1 = bhh[2 * Hd + fi0 + 1];
    }
    __syncthreads();

    const u64* WpR = Wp + (0 * 4 + cg) * WPS;
    const u64* WpZ = Wp + (1 * 4 + cg) * WPS;
    const u64* WpN = Wp + (2 * 4 + cg) * WPS;

    for (int t = 0; t < Wt; t++) {
        const float* hsrc = g_h + (size_t)t * Hd * Bv;

        // prefetch gate-stage operands (consumed at end of step)
        float2 gir, giz, gin;
        float hp0 = 0.f, hp1 = 0.f;
        if (tid < 128) {
            const float* gi = g_xW + ((size_t)t * Bv + fb) * G3 + fi0;
            gir = __ldcg((const float2*)gi);
            giz = __ldcg((const float2*)(gi + Hd));
            gin = __ldcg((const float2*)(gi + 2 * Hd));
            hp0 = __ldcg(hsrc + fi0 * Bv + fb);
            hp1 = __ldcg(hsrc + (fi0 + 1) * Bv + fb);
        }

        u64 aR[8], aZ[8], aN[8];
#pragma unroll
        for (int j = 0; j < 8; j++) { aR[j] = 0ULL; aZ[j] = 0ULL; aN[j] = 0ULL; }

        // ---- stage chunk 0 ----
#pragma unroll
        for (int it = 0; it < 8; it++) {
            int q = it * TPB + tid;
            int kl = q >> 3, b4 = q & 7;
            float4 v = __ldcg((const float4*)(hsrc + kl * Bv + b4 * 4));
            *(float4*)(hb + kl * HBROW + b4 * 4) = v;
        }
        __syncthreads();

        for (int ch = 0; ch < 4; ch++) {
            int buf = ch & 1;
            if (ch < 3) {
                const float* src = hsrc + (ch + 1) * 256 * Bv;
                float* dst = hb + (buf ^ 1) * HBN;
#pragma unroll
                for (int it = 0; it < 8; it++) {
                    int q = it * TPB + tid;
                    int kl = q >> 3, b4 = q & 7;
                    float4 v = __ldcg((const float4*)(src + kl * Bv + b4 * 4));
                    *(float4*)(dst + kl * HBROW + b4 * 4) = v;
                }
            }
            const float* hbuf = hb + buf * HBN;
            const u64* wR = WpR + ch * 256;
            const u64* wZ = WpZ + ch * 256;
            const u64* wN = WpN + ch * 256;
#pragma unroll 4
            for (int kk = 0; kk < 16; kk++) {
                int kl = sbase + kk;
                const float4* hp4 = (const float4*)(hbuf + kl * HBROW + bg * 8);
                float4 h0 = hp4[0];
                float4 h1 = hp4[1];
                u64 vr = wR[kl], vz = wZ[kl], vn = wN[kl];
                u64 d;
                d = dup2(h0.x); ffma2(aR[0], d, vr); ffma2(aZ[0], d, vz); ffma2(aN[0], d, vn);
                d = dup2(h0.y); ffma2(aR[1], d, vr); ffma2(aZ[1], d, vz); ffma2(aN[1], d, vn);
                d = dup2(h0.z); ffma2(aR[2], d, vr); ffma2(aZ[2], d, vz); ffma2(aN[2], d, vn);
                d = dup2(h0.w); ffma2(aR[3], d, vr); ffma2(aZ[3], d, vz); ffma2(aN[3], d, vn);
                d = dup2(h1.x); ffma2(aR[4], d, vr); ffma2(aZ[4], d, vz); ffma2(aN[4], d, vn);
                d = dup2(h1.y); ffma2(aR[5], d, vr); ffma2(aZ[5], d, vz); ffma2(aN[5], d, vn);
                d = dup2(h1.z); ffma2(aR[6], d, vr); ffma2(aZ[6], d, vz); ffma2(aN[6], d, vn);
                d = dup2(h1.w); ffma2(aR[7], d, vr); ffma2(aZ[7], d, vz); ffma2(aN[7], d, vn);
            }
            __syncthreads();
        }

        // ---- pair slices via shuffle (16 -> 8 partials) ----
#pragma unroll
        for (int j = 0; j < 8; j++) {
            aR[j] = fadd2(aR[j], __shfl_xor_sync(0xffffffffu, aR[j], 16));
            aZ[j] = fadd2(aZ[j], __shfl_xor_sync(0xffffffffu, aZ[j], 16));
            aN[j] = fadd2(aN[j], __shfl_xor_sync(0xffffffffu, aN[j], 16));
        }
        if ((tid & 31) < 16) {
            u64* rr = red + ((tid >> 5) * 16 + l) * 25;
#pragma unroll
            for (int j = 0; j < 8; j++) {
                rr[j] = aR[j]; rr[8 + j] = aZ[j]; rr[16 + j] = aN[j];
            }
        }
        __syncthreads();

        // ---- final: reduce 8 warps, gates, store h_new ----
        if (tid < 128) {
            u64 sR = 0ULL, sZ = 0ULL, sN = 0ULL;
#pragma unroll
            for (int w = 0; w < 8; w++) {
                const u64* rb = red + (w * 16 + flsel) * 25;
                sR = fadd2(sR, rb[fbi]);
                sZ = fadd2(sZ, rb[8 + fbi]);
                sN = fadd2(sN, rb[16 + fbi]);
            }
            float gr0 = gir.x + lo32(sR) + bhr0;
            float gr1 = gir.y + hi32(sR) + bhr1;
            float gz0 = giz.x + lo32(sZ) + bhz0;
            float gz1 = giz.y + hi32(sZ) + bhz1;
            float rr0 = 1.f / (1.f + __expf(-gr0));
            float rr1 = 1.f / (1.f + __expf(-gr1));
            float zz0 = 1.f / (1.f + __expf(-gz0));
            float zz1 = 1.f / (1.f + __expf(-gz1));
            float nn0 = tanhf(gin.x + rr0 * (lo32(sN) + bhn0));
            float nn1 = tanhf(gin.y + rr1 * (hi32(sN) + bhn1));
            float* hdst = g_h + (size_t)(t + 1) * Hd * Bv;
            hdst[fi0 * Bv + fb] = (1.f - zz0) * nn0 + zz0 * hp0;
            hdst[(fi0 + 1) * Bv + fb] = (1.f - zz1) * nn1 + zz1 * hp1;
        }

        gridBarrier();
    }
}

// ------------------------- K3: denseH = h_all @ Wd[:,100:]^T + bd ------------
// M=8192 (4 t x 32 b per block), N=128 (100 valid), K=1024. 64 blocks.
__global__ __launch_bounds__(256) void k_dh(const float* __restrict__ Wd,
                                            const float* __restrict__ bd) {
    __shared__ float As[8][132];
    __shared__ float Bs[8][128];
    int tid = threadIdx.x;
    int tbase = blockIdx.x * 4;           // 4 timesteps per block
    int m0 = blockIdx.x * 128;

    int akk = tid >> 5;
    int au = tid & 31;
    int atsub = au >> 3;
    int ab4 = au & 7;

    int bRow = tid >> 1;
    int bK = (tid & 1) * 4;
    const float* bptr = Wd + (size_t)bRow * (Zd + Hd) + Zd + bK;
    bool bValid = (bRow < Dd);

    int tr = tid >> 4;
    int tc = tid & 15;

    u64 acc[8][4];
#pragma unroll
    for (int i = 0; i < 8; i++)
#pragma unroll
        for (int j = 0; j < 4; j++) acc[i][j] = 0ULL;

    for (int k0 = 0; k0 < Hd; k0 += 8) {
        // A from hT: hT[t+1][k][b]
        {
            const float* src = g_h +
                ((size_t)(tbase + atsub + 1) * Hd + (k0 + akk)) * Bv + ab4 * 4;
            float4 v = *(const float4*)src;
            *(float4*)&As[akk][atsub * 32 + ab4 * 4] = v;
        }
        {
            float4 v = bValid ? *(const float4*)(bptr + k0)
                              : make_float4(0.f, 0.f, 0.f, 0.f);
            Bs[bK + 0][bRow] = v.x; Bs[bK + 1][bRow] = v.y;
            Bs[bK + 2][bRow] = v.z; Bs[bK + 3][bRow] = v.w;
        }
        __syncthreads();
#pragma unroll
        for (int k = 0; k < 8; k++) {
            u64 bp[4];
#pragma unroll
            for (int j = 0; j < 4; j++)
                bp[j] = *(const u64*)&Bs[k][tc * 8 + 2 * j];
#pragma unroll
            for (int i = 0; i < 8; i++) {
                u64 ad = dup2(As[k][tr * 8 + i]);
#pragma unroll
                for (int j = 0; j < 4; j++) ffma2(acc[i][j], ad, bp[j]);
            }
        }
        __syncthreads();
    }

#pragma unroll
    for (int i = 0; i < 8; i++) {
        size_t row = (size_t)(m0 + tr * 8 + i);
#pragma unroll
        for (int j = 0; j < 4; j++) {
            int col = tc * 8 + 2 * j;
            if (col < Dd) {
                g_dh[row * Dd + col] = lo32(acc[i][j]) + bd[col];
                g_dh[row * Dd + col + 1] = hi32(acc[i][j]) + bd[col + 1];
            }
        }
    }
}

// ------------------------- K4: batch-parallel z-chain ------------------------
__global__ void k_head(const float* __restrict__ Wd,
                       const float* __restrict__ Wmu, const float* __restrict__ bmu,
                       const float* __restrict__ Wsig, const float* __restrict__ bsig,
                       const float* __restrict__ u,
                       const float* __restrict__ Wpnf, const float* __restrict__ bpnf,
                       const float* __restrict__ noise,
                       float* __restrict__ out) {
    extern __shared__ float smh[];
    float* Wdz = smh;
    float* Wmu_t = Wdz + 10000;
    float* Wsg_t = Wmu_t + 10000;
    float* Wpf_t = Wsg_t + 10000;
    float* zb = Wpf_t + 10000;
    float* dn = zb + 104;
    float* zm = dn + 104;

    int b = blockIdx.x;
    int tid = threadIdx.x;

    for (int i = tid; i < 10000; i += 128) {
        int j = i / 100, k = i - j * 100;
        Wdz[k * 100 + j] = Wd[(size_t)j * (Zd + Hd) + k];
        Wmu_t[k * 100 + j] = Wmu[(size_t)j * 100 + k];
        Wsg_t[k * 100 + j] = Wsig[(size_t)j * 100 + k];
        Wpf_t[k * 100 + j] = Wpnf[(size_t)j * 100 + k];
    }
    if (tid < 100) zb[tid] = 0.f;
    __syncthreads();

    float u0 = u[0];
    const size_t BWZ = (size_t)Bv * Wt * Zd;

    for (int t = 0; t < Wt; t++) {
        if (tid < 100) {
            float s = g_dh[((size_t)t * Bv + b) * Dd + tid];
#pragma unroll 4
            for (int k = 0; k < 100; k++) s += zb[k] * Wdz[k * 100 + tid];
            dn[tid] = s;
        }
        __syncthreads();
        if (tid < 100) {
            float smu = bmu[tid], ssg = bsig[tid];
#pragma unroll 4
            for (int k = 0; k < 100; k++) {
                float d = dn[k];
                smu += d * Wmu_t[k * 100 + tid];
                ssg += d * Wsg_t[k * 100 + tid];
            }
            float lv = fmaxf(ssg, 0.f) + log1pf(expf(-fabsf(ssg)));
            float eps = noise[((size_t)t * Bv + b) * Zd + tid];
            float zmid = smu + expf(0.5f * lv) * eps;
            zm[tid] = zmid;
            size_t o = ((size_t)b * Wt + t) * Zd + tid;
            out[BWZ + o] = smu;
            out[2 * BWZ + o] = lv;
        }
        __syncthreads();
        if (tid < 100) {
            float s = bpnf[tid];
#pragma unroll 4
            for (int k = 0; k < 100; k++) s += zm[k] * Wpf_t[k * 100 + tid];
            float zn = zm[tid] + u0 * tanhf(s);
            zb[tid] = zn;
            out[((size_t)b * Wt + t) * Zd + tid] = zn;
        }
        __syncthreads();
    }
}

// ------------------------- launch -------------------------------------------
extern "C" void kernel_launch(void* const* d_in, const int* in_sizes, int n_in,
                              void* d_out, int out_size) {
    const float* x = (const float*)d_in[0];
    const float* Wih = (const float*)d_in[1];
    const float* Whh = (const float*)d_in[2];
    const float* bih = (const float*)d_in[3];
    const float* bhh = (const float*)d_in[4];
    const float* Wd = (const float*)d_in[5];
    const float* bd = (const float*)d_in[6];
    const float* Wmu = (const float*)d_in[7];
    const float* bmu = (const float*)d_in[8];
    const float* Wsig = (const float*)d_in[9];
    const float* bsig = (const float*)d_in[10];
    const float* u = (const float*)d_in[11];
    const float* Wpnf = (const float*)d_in[12];
    const float* bpnf = (const float*)d_in[13];
    const float* noise = (const float*)d_in[14];
    float* out = (float*)d_out;

    k_init<<<(Bv * Hd + 255) / 256, 256>>>();
    k_xw<<<dim3(G3 / 128, (Wt * Bv) / 128), 256>>>(x, Wih, bih);

    cudaFuncSetAttribute(k_rnn, cudaFuncAttributeMaxDynamicSharedMemorySize,
                         RNN_SMEM);
    k_rnn<<<NCTA, TPB, RNN_SMEM>>>(Whh, bhh);

    k_dh<<<(Wt * Bv) / 128, 256>>>(Wd, bd);

    int smem_head = (4 * 10000 + 3 * 104) * (int)sizeof(float);
    cudaFuncSetAttribute(k_head, cudaFuncAttributeMaxDynamicSharedMemorySize,
                         smem_head);
    k_head<<<Bv, 128, smem_head>>>(Wd, Wmu, bmu, Wsig, bsig, u, Wpnf, bpnf,
                                   noise, out);
}